// round 13
// baseline (speedup 1.0000x reference)
#include <cuda_runtime.h>
#include <math.h>

#define BB 4
#define HH 8
#define LL 1024
#define DD 32
#define DIMM 256
#define ATT_SCALE 0.0625f   // DIM^-0.5 = 1/16

#define M1 1048576
// scratch layout (floats)
#define OFF_XQ   (0*M1)
#define OFF_XK   (1*M1)
#define OFF_XV   (2*M1)
#define OFF_RV   (3*M1)
#define OFF_Q    (4*M1)
#define OFF_K    (5*M1)
#define OFF_VM   (6*M1)
#define OFF_VRA  (7*M1)
#define OFF_VRB  (8*M1)
#define OFF_PCOL  (9*M1)                    // 128 xblk x 32 bi x 1024 t = 4*M1
#define OFF_RCINV (13*M1)                   // 32 bi x 1024 t
#define OFF_MASK  (13*M1 + 32768)           // bitmask, 1*M1 words (4 MB)

__device__ float g_scratch[14*M1 + 32768];

// packed fp32x2 helpers (sm_100+)
#define FMA2(acc, a, b) \
    asm("fma.rn.f32x2 %0, %1, %2, %0;" : "+l"(acc) : "l"(a), "l"(b))
#define DUP2(dst, v) \
    asm("mov.b64 %0, {%1, %1};" : "=l"(dst) : "f"(v))
#define UNPACK2(lo, hi, v) \
    asm("mov.b64 {%0, %1}, %2;" : "=f"(lo), "=f"(hi) : "l"(v))

// ---------------------------------------------------------------------------
// K1: per-head projections  dst[b,h,t,d] = sum_dp src[b,t,h*32+dp] * W[dp,d]
// ---------------------------------------------------------------------------
__global__ __launch_bounds__(256) void proj_kernel(
    const float* __restrict__ x, const float* __restrict__ rx,
    const float* __restrict__ Wq, const float* __restrict__ Wk,
    const float* __restrict__ Wv, float* __restrict__ scratch)
{
    int tid = threadIdx.x;
    int which = blockIdx.y;
    const float* src = (which == 0 || which == 2) ? x : rx;
    const float* W = (which == 0) ? Wq : ((which == 1) ? Wk : Wv);
    float* dst = scratch + (size_t)which * M1;

    __shared__ float Ws[1024];
    __shared__ float Xs[8][32];
    for (int i = tid; i < 1024; i += 256) Ws[i] = W[i];

    int r = blockIdx.x * 8 + (tid >> 5);   // r = (b*8+h)*1024 + t
    int d = tid & 31;
    int b = r >> 13;
    int h = (r >> 10) & 7;
    int t = r & 1023;
    Xs[tid >> 5][d] = src[((size_t)(b * LL + t)) * DIMM + h * 32 + d];
    __syncthreads();

    float acc = 0.f;
    #pragma unroll
    for (int dp = 0; dp < 32; dp++) acc += Xs[tid >> 5][dp] * Ws[dp * 32 + d];
    dst[(size_t)r * 32 + d] = acc;
}

// ---------------------------------------------------------------------------
// K2: SPARSE binary gather-sum + adjacency bitmask emission (z==0 only).
// O[bh][l][d] = sum_{t: G[l][t] > 0} X[t][d].  mask word (t0>>7)*4+c holds
// ballot bits: bit lane <-> t = t0 + lane*4 + c.
// ---------------------------------------------------------------------------
__global__ __launch_bounds__(256) void spmm_binary(
    const float* __restrict__ G0, const float* __restrict__ X0, float* __restrict__ O0,
    const float* __restrict__ G1, const float* __restrict__ X1, float* __restrict__ O1,
    unsigned* __restrict__ maskOut)
{
    int lane = threadIdx.x & 31, w = threadIdx.x >> 5;
    int l = blockIdx.x * 8 + w;
    int bh = blockIdx.y;
    int z = blockIdx.z;
    const float* G = (z ? G1 : G0) + (size_t)bh * (LL * LL) + (size_t)l * LL;
    const float* X = (z ? X1 : X0) + (size_t)bh * (LL * DD);
    float* O = (z ? O1 : O0) + (size_t)bh * (LL * DD);
    unsigned* mrow = maskOut + ((size_t)bh * LL + l) * 32;

    float acc0 = 0.f, acc1 = 0.f;
    for (int t0 = 0; t0 < LL; t0 += 128) {
        float4 g = *(const float4*)&G[t0 + lane * 4];
        #pragma unroll
        for (int c = 0; c < 4; c++) {
            float gv = (c == 0) ? g.x : (c == 1) ? g.y : (c == 2) ? g.z : g.w;
            unsigned mb = __ballot_sync(0xffffffffu, gv > 0.f);
            if (z == 0 && lane == 0) mrow[(t0 >> 7) * 4 + c] = mb;
            unsigned m = mb;
            while (m) {
                int j = __ffs(m) - 1; m &= m - 1;
                acc0 += X[(t0 + j * 4 + c) * DD + lane];
                if (m) {
                    j = __ffs(m) - 1; m &= m - 1;
                    acc1 += X[(t0 + j * 4 + c) * DD + lane];
                }
            }
        }
    }
    O[(size_t)l * DD + lane] = acc0 + acc1;
}

// ---------------------------------------------------------------------------
// K2b (FUSED): SPARSE weighted gather + transposed-softmax column partials.
//   VM[b,l,h*32+d] = sum_{t: A[l][t] > 0} A[l][t]*X[t][d]
//   pcol[xblk][bi][t] = sum_{l in xblk} exp(A[l][t])   (ALL t, exp(0)=1)
// Per-warp lane-private smem bins; block reduce in fixed warp order.
// ---------------------------------------------------------------------------
__global__ __launch_bounds__(256) void spmm_weighted(
    const float* __restrict__ A, const float* __restrict__ X,
    float* __restrict__ O, float* __restrict__ pcol)
{
    __shared__ float colsm[8][1024];
    int tid = threadIdx.x;
    int lane = tid & 31, w = tid >> 5;
    int l = blockIdx.x * 8 + w;
    int bh = blockIdx.y;
    int b = bh >> 3, h = bh & 7;
    const float* G = A + (size_t)bh * (LL * LL) + (size_t)l * LL;
    const float* Xb = X + (size_t)bh * (LL * DD);

    for (int i = lane; i < 1024; i += 32) colsm[w][i] = 0.f;
    __syncwarp();

    float acc0 = 0.f, acc1 = 0.f;
    for (int t0 = 0; t0 < LL; t0 += 128) {
        float4 g = *(const float4*)&G[t0 + lane * 4];
        #pragma unroll
        for (int c = 0; c < 4; c++) {
            float gv = (c == 0) ? g.x : (c == 1) ? g.y : (c == 2) ? g.z : g.w;
            // column partial: slot = ((t>>7)*4 + (t&3))*32 + ((t&127)>>2)
            colsm[w][((t0 >> 7) * 4 + c) * 32 + lane] += __expf(gv);
            unsigned m = __ballot_sync(0xffffffffu, gv > 0.f);
            while (m) {
                int j = __ffs(m) - 1; m &= m - 1;
                float av = __shfl_sync(0xffffffffu, gv, j);
                acc0 += av * Xb[(t0 + j * 4 + c) * DD + lane];
                if (m) {
                    j = __ffs(m) - 1; m &= m - 1;
                    float av2 = __shfl_sync(0xffffffffu, gv, j);
                    acc1 += av2 * Xb[(t0 + j * 4 + c) * DD + lane];
                }
            }
        }
    }
    O[(size_t)b * (LL * DIMM) + (size_t)l * DIMM + h * 32 + lane] = acc0 + acc1;

    __syncthreads();
    // block reduce 8 warps, fixed order; write partial for this l-chunk
    for (int t = tid; t < 1024; t += 256) {
        int slot = ((t >> 7) * 4 + (t & 3)) * 32 + ((t & 127) >> 2);
        float s = 0.f;
        #pragma unroll
        for (int ww = 0; ww < 8; ww++) s += colsm[ww][slot];
        pcol[((size_t)blockIdx.x * 32 + bh) * LL + t] = s;
    }
}

// ---------------------------------------------------------------------------
// K2c: rcinv[bi][t] = 1 / sum_{x=0..127} pcol[x][bi][t]   (fixed order)
// ---------------------------------------------------------------------------
__global__ __launch_bounds__(256) void rc_combine_kernel(
    const float* __restrict__ pcol, float* __restrict__ rcinv)
{
    int i = blockIdx.x * 256 + threadIdx.x;   // 32768
    int bi = i >> 10, t = i & 1023;
    float s = 0.f;
    for (int x = 0; x < 128; x++)
        s += pcol[((size_t)x * 32 + bi) * LL + t];
    rcinv[i] = 1.f / s;
}

// ---------------------------------------------------------------------------
// K3a: S[bh][l][t] = leaky(ATT_SCALE * dot(q[bh][l], k[bh][t]))
// 128x64 tile, 8l x 4t per thread, packed FMA.
// ---------------------------------------------------------------------------
__global__ __launch_bounds__(256) void qk_gemm(
    const float* __restrict__ q, const float* __restrict__ k,
    float* __restrict__ S)
{
    __shared__ float Qt[32][132];   // [d][l]
    __shared__ float Kt[32][68];    // [d][t]

    int tid = threadIdx.x;
    int bh = blockIdx.z;
    int t0 = blockIdx.x * 64, l0 = blockIdx.y * 128;
    const float* qb = q + (size_t)bh * (LL * DD);
    const float* kb = k + (size_t)bh * (LL * DD);

    {
        int r = tid >> 1, cs = (tid & 1) * 16;
        #pragma unroll
        for (int j = 0; j < 4; j++) {
            float4 v = *(const float4*)(qb + (size_t)(l0 + r) * DD + cs + j * 4);
            Qt[cs + j*4 + 0][r] = v.x; Qt[cs + j*4 + 1][r] = v.y;
            Qt[cs + j*4 + 2][r] = v.z; Qt[cs + j*4 + 3][r] = v.w;
        }
    }
    {
        int r2 = tid & 63, cs2 = (tid >> 6) * 8;
        #pragma unroll
        for (int j = 0; j < 2; j++) {
            float4 v = *(const float4*)(kb + (size_t)(t0 + r2) * DD + cs2 + j * 4);
            Kt[cs2 + j*4 + 0][r2] = v.x; Kt[cs2 + j*4 + 1][r2] = v.y;
            Kt[cs2 + j*4 + 2][r2] = v.z; Kt[cs2 + j*4 + 3][r2] = v.w;
        }
    }
    __syncthreads();

    int lg = (tid >> 4) * 8;
    int tg = (tid & 15) * 4;
    unsigned long long acc2[4][4];
    #pragma unroll
    for (int t = 0; t < 4; t++)
        #pragma unroll
        for (int p = 0; p < 4; p++) acc2[t][p] = 0ULL;

    #pragma unroll
    for (int d = 0; d < 32; d++) {
        ulonglong2 q0 = *(const ulonglong2*)&Qt[d][lg];
        ulonglong2 q1 = *(const ulonglong2*)&Qt[d][lg + 4];
        float4 kv = *(const float4*)&Kt[d][tg];
        const float kl[4] = {kv.x, kv.y, kv.z, kv.w};
        #pragma unroll
        for (int t = 0; t < 4; t++) {
            unsigned long long k2;
            DUP2(k2, kl[t]);
            FMA2(acc2[t][0], q0.x, k2);
            FMA2(acc2[t][1], q0.y, k2);
            FMA2(acc2[t][2], q1.x, k2);
            FMA2(acc2[t][3], q1.y, k2);
        }
    }

    float* Sb = S + (size_t)bh * (LL * LL);
    #pragma unroll
    for (int r = 0; r < 8; r++) {
        float4 o;
        #pragma unroll
        for (int t = 0; t < 4; t++) {
            float lo, hi;
            UNPACK2(lo, hi, acc2[t][r >> 1]);
            float val = ((r & 1) ? hi : lo) * ATT_SCALE;
            ((float*)&o)[t] = (val > 0.f) ? val : 0.01f * val;
        }
        *(float4*)(Sb + (size_t)(l0 + lg + r) * LL + t0 + tg) = o;
    }
}

// ---------------------------------------------------------------------------
// K3b (FUSED softmax, bitmask): A = softmax_t( mask( sum_h R[i,h]*S ) )
// Mask from packed ballots (1 KB/block) instead of a 134 MB adj read.
// ---------------------------------------------------------------------------
__global__ __launch_bounds__(256) void mix_softmax_kernel(
    const float* __restrict__ S, const unsigned* __restrict__ maskBuf,
    const float* __restrict__ R, float* __restrict__ A_out)
{
    __shared__ float Rs[64];
    __shared__ unsigned Msk[8][32];
    __shared__ float red[8][8];    // [warp][i]
    __shared__ float bc_mx[8];
    __shared__ float bc_ri[8];
    int tid = threadIdx.x, lane = tid & 31, w = tid >> 5;
    int l = blockIdx.x, b = blockIdx.y;
    if (tid < 64) Rs[tid] = R[tid];
    Msk[tid >> 5][tid & 31] =
        maskBuf[((size_t)(b * 8 + (tid >> 5)) * LL + l) * 32 + (tid & 31)];
    __syncthreads();

    int t4 = tid * 4;
    int jbit = (t4 & 127) >> 2;
    int wbase = (t4 >> 7) * 4;
    float4 s[8];
    #pragma unroll
    for (int h = 0; h < 8; h++)
        s[h] = *(const float4*)(S + ((size_t)((b * 8 + h) * LL + l)) * LL + t4);

    float4 o[8];
    float rmax[8];
    #pragma unroll
    for (int i = 0; i < 8; i++) {
        float mx = 0.f, my = 0.f, mz = 0.f, mw = 0.f;
        #pragma unroll
        for (int h = 0; h < 8; h++) {
            float r = Rs[i * 8 + h];
            mx += r * s[h].x; my += r * s[h].y;
            mz += r * s[h].z; mw += r * s[h].w;
        }
        unsigned w0 = Msk[i][wbase + 0], w1 = Msk[i][wbase + 1];
        unsigned w2 = Msk[i][wbase + 2], w3 = Msk[i][wbase + 3];
        o[i].x = ((w0 >> jbit) & 1u) ? mx : -INFINITY;
        o[i].y = ((w1 >> jbit) & 1u) ? my : -INFINITY;
        o[i].z = ((w2 >> jbit) & 1u) ? mz : -INFINITY;
        o[i].w = ((w3 >> jbit) & 1u) ? mw : -INFINITY;
        rmax[i] = fmaxf(fmaxf(o[i].x, o[i].y), fmaxf(o[i].z, o[i].w));
    }

    #pragma unroll
    for (int i = 0; i < 8; i++) {
        float mx = rmax[i];
        #pragma unroll
        for (int off = 16; off; off >>= 1)
            mx = fmaxf(mx, __shfl_down_sync(0xffffffffu, mx, off));
        if (lane == 0) red[w][i] = mx;
    }
    __syncthreads();
    if (tid < 8) {
        float mx = red[0][tid];
        #pragma unroll
        for (int ww = 1; ww < 8; ww++) mx = fmaxf(mx, red[ww][tid]);
        bc_mx[tid] = mx;
    }
    __syncthreads();

    float psum[8];
    #pragma unroll
    for (int i = 0; i < 8; i++) {
        float mx = bc_mx[i];
        o[i].x = __expf(o[i].x - mx);
        o[i].y = __expf(o[i].y - mx);
        o[i].z = __expf(o[i].z - mx);
        o[i].w = __expf(o[i].w - mx);
        psum[i] = (o[i].x + o[i].y) + (o[i].z + o[i].w);
    }
    __syncthreads();
    #pragma unroll
    for (int i = 0; i < 8; i++) {
        float sm = psum[i];
        #pragma unroll
        for (int off = 16; off; off >>= 1)
            sm += __shfl_down_sync(0xffffffffu, sm, off);
        if (lane == 0) red[w][i] = sm;
    }
    __syncthreads();
    if (tid < 8) {
        float sm = 0.f;
        #pragma unroll
        for (int ww = 0; ww < 8; ww++) sm += red[ww][tid];
        bc_ri[tid] = 1.f / sm;
    }
    __syncthreads();

    #pragma unroll
    for (int i = 0; i < 8; i++) {
        float ri = bc_ri[i];
        float4 a;
        a.x = o[i].x * ri; a.y = o[i].y * ri;
        a.z = o[i].z * ri; a.w = o[i].w * ri;
        *(float4*)(A_out + ((size_t)((b * 8 + i) * LL + l)) * LL + t4) = a;
    }
}

// ---------------------------------------------------------------------------
// K5 (FUSED): Ar tile construction + write + GEMM, per (b,h), k-split z.
// ---------------------------------------------------------------------------
__global__ __launch_bounds__(256) void gemm_ar(
    const float* __restrict__ A, const float* __restrict__ rcinv,
    const float* __restrict__ Bm, float* __restrict__ ArOut,
    float* __restrict__ Cp0, float* __restrict__ Cp1)
{
    __shared__ float Ast[32][132];   // [l][t] holding Ar values
    __shared__ float Bs[32][32];     // [l][n]

    int tid = threadIdx.x;
    int bh = blockIdx.y;
    int kz = blockIdx.z;
    int t0 = blockIdx.x * 128;
    const float* Ab  = A + (size_t)bh * (LL * LL);
    const float* Bb  = Bm + (size_t)bh * (LL * DD);
    const float* rcb = rcinv + bh * LL;
    float* Arb = ArOut + (size_t)bh * (LL * LL);
    float* C = (kz ? Cp1 : Cp0) + (size_t)(bh >> 3) * (LL * DIMM);
    int hh = bh & 7;

    int lr = tid >> 3, tseg = (tid & 7) * 16;
    int brow = tid >> 3, bcol = (tid & 7) * 4;
    int rg4 = (tid >> 3) * 4, cg = (tid & 7) * 4;

    unsigned long long acc2[4][2];
    #pragma unroll
    for (int c4 = 0; c4 < 4; c4++) { acc2[c4][0] = 0ULL; acc2[c4][1] = 0ULL; }

    for (int c = 0; c < 16; c++) {
        int l0 = kz * 512 + c * 32;
        #pragma unroll
        for (int j = 0; j < 4; j++) {
            float4 v  = *(const float4*)(Ab + (size_t)(l0 + lr) * LL + t0 + tseg + j * 4);
            float4 rc = *(const float4*)(rcb + t0 + tseg + j * 4);
            float4 ar;
            ar.x = __expf(v.x) * rc.x; ar.y = __expf(v.y) * rc.y;
            ar.z = __expf(v.z) * rc.z; ar.w = __expf(v.w) * rc.w;
            *(float4*)&Ast[lr][tseg + j * 4] = ar;
        }
        *(float4*)&Bs[brow][bcol] =
            *(const float4*)(Bb + (size_t)(l0 + brow) * DD + bcol);
        __syncthreads();

        #pragma unroll
        for (int p = 0; p < 4; p++) {
            int tr = p * 32 + (tid >> 3);
            int lc = (tid & 7) * 4;
            float4 wv;
            wv.x = Ast[lc + 0][tr]; wv.y = Ast[lc + 1][tr];
            wv.z = Ast[lc + 2][tr]; wv.w = Ast[lc + 3][tr];
            *(float4*)(Arb + (size_t)(t0 + tr) * LL + l0 + lc) = wv;
        }

        #pragma unroll
        for (int kk = 0; kk < 32; kk++) {
            ulonglong2 ap = *(const ulonglong2*)&Ast[kk][rg4];
            float4 bv = *(const float4*)&Bs[kk][cg];
            const float bl[4] = {bv.x, bv.y, bv.z, bv.w};
            #pragma unroll
            for (int c4 = 0; c4 < 4; c4++) {
                unsigned long long b2;
                DUP2(b2, bl[c4]);
                FMA2(acc2[c4][0], ap.x, b2);
                FMA2(acc2[c4][1], ap.y, b2);
            }
        }
        __syncthreads();
    }

    #pragma unroll
    for (int r = 0; r < 4; r++) {
        float4 o;
        #pragma unroll
        for (int c4 = 0; c4 < 4; c4++) {
            float lo, hi;
            UNPACK2(lo, hi, acc2[c4][r >> 1]);
            ((float*)&o)[c4] = (r & 1) ? hi : lo;
        }
        *(float4*)(C + (size_t)(t0 + rg4 + r) * DIMM + hh * 32 + cg) = o;
    }
}

// ---------------------------------------------------------------------------
// K6: Out[r,n] = sum_m gelu(Vm[r,m]) * Wp[m,n]. 128x32 tile, 4x4 thread tile.
// ---------------------------------------------------------------------------
__device__ __forceinline__ float gelu_exact(float v)
{
    return 0.5f * v * (1.f + erff(v * 0.70710678118654752f));
}

__global__ __launch_bounds__(256) void out_gemm(
    const float* __restrict__ V0, const float* __restrict__ V1a,
    const float* __restrict__ V1b, const float* __restrict__ Wp,
    float* __restrict__ O0, float* __restrict__ O1)
{
    __shared__ float Gs[32][132];
    __shared__ float Ws[32][32];
    int z = blockIdx.z;
    float* Out = z ? O1 : O0;
    int tid = threadIdx.x;
    int r0 = blockIdx.x * 128, n0 = blockIdx.y * 32;

    int lrow = tid >> 1, cseg = (tid & 1) * 16;
    int brow = tid >> 3, bcol = (tid & 7) * 4;
    int rg4 = (tid >> 3) * 4;
    int cg  = (tid & 7) * 4;

    unsigned long long acc2[4][2];
    #pragma unroll
    for (int c4 = 0; c4 < 4; c4++) { acc2[c4][0] = 0ULL; acc2[c4][1] = 0ULL; }

    for (int k0 = 0; k0 < DIMM; k0 += 32) {
        size_t roff = (size_t)(r0 + lrow) * DIMM + k0 + cseg;
        #pragma unroll
        for (int j = 0; j < 4; j++) {
            float4 a;
            if (z) {
                float4 p0 = *(const float4*)(V1a + roff + j * 4);
                float4 p1 = *(const float4*)(V1b + roff + j * 4);
                a.x = p0.x + p1.x; a.y = p0.y + p1.y;
                a.z = p0.z + p1.z; a.w = p0.w + p1.w;
            } else {
                a = *(const float4*)(V0 + roff + j * 4);
            }
            Gs[cseg + j*4 + 0][lrow] = gelu_exact(a.x);
            Gs[cseg + j*4 + 1][lrow] = gelu_exact(a.y);
            Gs[cseg + j*4 + 2][lrow] = gelu_exact(a.z);
            Gs[cseg + j*4 + 3][lrow] = gelu_exact(a.w);
        }
        *(float4*)&Ws[brow][bcol] =
            *(const float4*)(Wp + (size_t)(k0 + brow) * DIMM + n0 + bcol);
        __syncthreads();

        #pragma unroll
        for (int kk = 0; kk < 32; kk++) {
            ulonglong2 ap = *(const ulonglong2*)&Gs[kk][rg4];
            float4 bv = *(const float4*)&Ws[kk][cg];
            const float bl[4] = {bv.x, bv.y, bv.z, bv.w};
            #pragma unroll
            for (int c4 = 0; c4 < 4; c4++) {
                unsigned long long b2;
                DUP2(b2, bl[c4]);
                FMA2(acc2[c4][0], ap.x, b2);
                FMA2(acc2[c4][1], ap.y, b2);
            }
        }
        __syncthreads();
    }

    #pragma unroll
    for (int r = 0; r < 4; r++) {
        float4 o;
        #pragma unroll
        for (int c4 = 0; c4 < 4; c4++) {
            float lo, hi;
            UNPACK2(lo, hi, acc2[c4][r >> 1]);
            ((float*)&o)[c4] = (r & 1) ? hi : lo;
        }
        *(float4*)(Out + (size_t)(r0 + rg4 + r) * DIMM + n0 + cg) = o;
    }
}

// ---------------------------------------------------------------------------
// Launch. Output layout (float32, reference return order):
//   out [4,1024,256] | out_resize [4,1024,256] | A [4,8,1024,1024] | Ar [...]
// S (QK^T logits) borrows the Ar region until gemm_ar overwrites it.
// ---------------------------------------------------------------------------
extern "C" void kernel_launch(void* const* d_in, const int* in_sizes, int n_in,
                              void* d_out, int out_size)
{
    const float* x    = (const float*)d_in[0];
    const float* rx   = (const float*)d_in[1];
    const float* adj  = (const float*)d_in[2];
    const float* adjr = (const float*)d_in[3];
    const float* Wq   = (const float*)d_in[4];
    const float* Wk   = (const float*)d_in[5];
    const float* Wv   = (const float*)d_in[6];
    const float* R    = (const float*)d_in[7];
    const float* Wp   = (const float*)d_in[8];

    float* out  = (float*)d_out;
    float* outr = out + (size_t)BB * LL * DIMM;
    float* A    = out + (size_t)2 * BB * LL * DIMM;
    float* Ar   = A + (size_t)BB * HH * LL * LL;

    float* s = nullptr;
    cudaGetSymbolAddress((void**)&s, g_scratch);
    unsigned* maskBuf = (unsigned*)(s + OFF_MASK);

    // K1: projections (xq, xk, xv, rv)
    proj_kernel<<<dim3(4096, 4), 256>>>(x, rx, Wq, Wk, Wv, s);

    // K2: q = adj @ xq ; k = adjr @ xk ; emit adjacency bitmask (z=0)
    spmm_binary<<<dim3(128, 32, 2), 256>>>(adj,  s + OFF_XQ, s + OFF_Q,
                                           adjr, s + OFF_XK, s + OFF_K,
                                           maskBuf);

    // K3a: S = leaky(scale * q @ k^T)  -> Ar region (scratch use)
    qk_gemm<<<dim3(16, 8, 32), 256>>>(s + OFF_Q, s + OFF_K, Ar);

    // K3b: R-mix + bitmask + full row softmax -> final A
    mix_softmax_kernel<<<dim3(1024, 4), 256>>>(Ar, maskBuf, R, A);

    // K4: v = A @ xv (sparse gather) + colsum partials, fused
    spmm_weighted<<<dim3(128, 32), 256>>>(A, s + OFF_XV, s + OFF_VM,
                                          s + OFF_PCOL);
    rc_combine_kernel<<<128, 256>>>(s + OFF_PCOL, s + OFF_RCINV);

    // K5: fused Ar construction + write + vr GEMM (k-split partials)
    gemm_ar<<<dim3(8, 32, 2), 256>>>(A, s + OFF_RCINV, s + OFF_RV, Ar,
                                     s + OFF_VRA, s + OFF_VRB);

    // K6: out = gelu(v) @ Wp ; out_resize = gelu(vra+vrb) @ Wp
    out_gemm<<<dim3(32, 8, 2), 256>>>(s + OFF_VM, s + OFF_VRA, s + OFF_VRB,
                                      Wp, out, outr);
}

// round 14
// speedup vs baseline: 1.0293x; 1.0293x over previous
#include <cuda_runtime.h>
#include <math.h>

#define BB 4
#define HH 8
#define LL 1024
#define DD 32
#define DIMM 256
#define ATT_SCALE 0.0625f   // DIM^-0.5 = 1/16

#define M1 1048576
// scratch layout (floats)
#define OFF_XQ   (0*M1)
#define OFF_XK   (1*M1)
#define OFF_XV   (2*M1)
#define OFF_RV   (3*M1)
#define OFF_Q    (4*M1)
#define OFF_K    (5*M1)
#define OFF_VM   (6*M1)
#define OFF_VRA  (7*M1)
#define OFF_VRB  (8*M1)
#define OFF_PCOL  (9*M1)                    // 4 segs x 32 bi x 1024 t
#define OFF_RCINV (9*M1 + 131072)           // 32 bi x 1024 t
#define OFF_MASK  (9*M1 + 163840)           // bitmask, 1*M1 words (4 MB)

__device__ float g_scratch[10*M1 + 163840];

// packed fp32x2 helpers (sm_100+)
#define FMA2(acc, a, b) \
    asm("fma.rn.f32x2 %0, %1, %2, %0;" : "+l"(acc) : "l"(a), "l"(b))
#define DUP2(dst, v) \
    asm("mov.b64 %0, {%1, %1};" : "=l"(dst) : "f"(v))
#define UNPACK2(lo, hi, v) \
    asm("mov.b64 {%0, %1}, %2;" : "=f"(lo), "=f"(hi) : "l"(v))

// ---------------------------------------------------------------------------
// K1: per-head projections  dst[b,h,t,d] = sum_dp src[b,t,h*32+dp] * W[dp,d]
// ---------------------------------------------------------------------------
__global__ __launch_bounds__(256) void proj_kernel(
    const float* __restrict__ x, const float* __restrict__ rx,
    const float* __restrict__ Wq, const float* __restrict__ Wk,
    const float* __restrict__ Wv, float* __restrict__ scratch)
{
    int tid = threadIdx.x;
    int which = blockIdx.y;
    const float* src = (which == 0 || which == 2) ? x : rx;
    const float* W = (which == 0) ? Wq : ((which == 1) ? Wk : Wv);
    float* dst = scratch + (size_t)which * M1;

    __shared__ float Ws[1024];
    __shared__ float Xs[8][32];
    for (int i = tid; i < 1024; i += 256) Ws[i] = W[i];

    int r = blockIdx.x * 8 + (tid >> 5);   // r = (b*8+h)*1024 + t
    int d = tid & 31;
    int b = r >> 13;
    int h = (r >> 10) & 7;
    int t = r & 1023;
    Xs[tid >> 5][d] = src[((size_t)(b * LL + t)) * DIMM + h * 32 + d];
    __syncthreads();

    float acc = 0.f;
    #pragma unroll
    for (int dp = 0; dp < 32; dp++) acc += Xs[tid >> 5][dp] * Ws[dp * 32 + d];
    dst[(size_t)r * 32 + d] = acc;
}

// ---------------------------------------------------------------------------
// K2: SPARSE binary gather-sum + adjacency bitmask emission (z==0 only).
// mask word (t0>>7)*4+c holds ballot bits: bit lane <-> t = t0 + lane*4 + c.
// ---------------------------------------------------------------------------
__global__ __launch_bounds__(256) void spmm_binary(
    const float* __restrict__ G0, const float* __restrict__ X0, float* __restrict__ O0,
    const float* __restrict__ G1, const float* __restrict__ X1, float* __restrict__ O1,
    unsigned* __restrict__ maskOut)
{
    int lane = threadIdx.x & 31, w = threadIdx.x >> 5;
    int l = blockIdx.x * 8 + w;
    int bh = blockIdx.y;
    int z = blockIdx.z;
    const float* G = (z ? G1 : G0) + (size_t)bh * (LL * LL) + (size_t)l * LL;
    const float* X = (z ? X1 : X0) + (size_t)bh * (LL * DD);
    float* O = (z ? O1 : O0) + (size_t)bh * (LL * DD);
    unsigned* mrow = maskOut + ((size_t)bh * LL + l) * 32;

    float acc0 = 0.f, acc1 = 0.f;
    for (int t0 = 0; t0 < LL; t0 += 128) {
        float4 g = *(const float4*)&G[t0 + lane * 4];
        #pragma unroll
        for (int c = 0; c < 4; c++) {
            float gv = (c == 0) ? g.x : (c == 1) ? g.y : (c == 2) ? g.z : g.w;
            unsigned mb = __ballot_sync(0xffffffffu, gv > 0.f);
            if (z == 0 && lane == 0) mrow[(t0 >> 7) * 4 + c] = mb;
            unsigned m = mb;
            while (m) {
                int j = __ffs(m) - 1; m &= m - 1;
                acc0 += X[(t0 + j * 4 + c) * DD + lane];
                if (m) {
                    j = __ffs(m) - 1; m &= m - 1;
                    acc1 += X[(t0 + j * 4 + c) * DD + lane];
                }
            }
        }
    }
    O[(size_t)l * DD + lane] = acc0 + acc1;
}

// ---------------------------------------------------------------------------
// K2b: SPARSE weighted gather:  VM[b,l,h*32+d] = sum_{t: A[l][t] > 0} A*X
// (lean R12 version — no colsum fusion; high occupancy)
// ---------------------------------------------------------------------------
__global__ __launch_bounds__(256) void spmm_weighted(
    const float* __restrict__ A, const float* __restrict__ X, float* __restrict__ O)
{
    int lane = threadIdx.x & 31, w = threadIdx.x >> 5;
    int l = blockIdx.x * 8 + w;
    int bh = blockIdx.y;
    int b = bh >> 3, h = bh & 7;
    const float* G = A + (size_t)bh * (LL * LL) + (size_t)l * LL;
    const float* Xb = X + (size_t)bh * (LL * DD);

    float acc0 = 0.f, acc1 = 0.f;
    for (int t0 = 0; t0 < LL; t0 += 128) {
        float4 g = *(const float4*)&G[t0 + lane * 4];
        #pragma unroll
        for (int c = 0; c < 4; c++) {
            float gv = (c == 0) ? g.x : (c == 1) ? g.y : (c == 2) ? g.z : g.w;
            unsigned m = __ballot_sync(0xffffffffu, gv > 0.f);
            while (m) {
                int j = __ffs(m) - 1; m &= m - 1;
                float av = __shfl_sync(0xffffffffu, gv, j);
                acc0 += av * Xb[(t0 + j * 4 + c) * DD + lane];
                if (m) {
                    j = __ffs(m) - 1; m &= m - 1;
                    float av2 = __shfl_sync(0xffffffffu, gv, j);
                    acc1 += av2 * Xb[(t0 + j * 4 + c) * DD + lane];
                }
            }
        }
    }
    O[(size_t)b * (LL * DIMM) + (size_t)l * DIMM + h * 32 + lane] = acc0 + acc1;
}

// ---------------------------------------------------------------------------
// K4: column partials: pcol[seg][bi][t] = sum_{l in seg} exp(A[l,t])
// (standalone streaming kernel — R12 version)
// ---------------------------------------------------------------------------
__global__ __launch_bounds__(256) void colsum_kernel(
    const float* __restrict__ A, float* __restrict__ pcol)
{
    int bi = blockIdx.y;
    int seg = blockIdx.z;
    int t = blockIdx.x * 256 + threadIdx.x;
    const float* base = A + (size_t)bi * (LL * LL);

    int lr0 = seg * 256;
    float s0 = 0.f, s1 = 0.f, s2 = 0.f, s3 = 0.f;
    for (int lr = lr0; lr < lr0 + 256; lr += 4) {
        s0 += __expf(base[(size_t)(lr + 0) * LL + t]);
        s1 += __expf(base[(size_t)(lr + 1) * LL + t]);
        s2 += __expf(base[(size_t)(lr + 2) * LL + t]);
        s3 += __expf(base[(size_t)(lr + 3) * LL + t]);
    }
    pcol[(size_t)(seg * 32 + bi) * LL + t] = (s0 + s1) + (s2 + s3);
}

// ---------------------------------------------------------------------------
// K4b: rcinv[bi][t] = 1 / (sum of 4 partials)
// ---------------------------------------------------------------------------
__global__ __launch_bounds__(256) void rc_combine_kernel(
    const float* __restrict__ pcol, float* __restrict__ rcinv)
{
    int i = blockIdx.x * 256 + threadIdx.x;   // 32768
    int bi = i >> 10, t = i & 1023;
    rcinv[i] = 1.f / (pcol[(size_t)(0 * 32 + bi) * LL + t]
                    + pcol[(size_t)(1 * 32 + bi) * LL + t]
                    + pcol[(size_t)(2 * 32 + bi) * LL + t]
                    + pcol[(size_t)(3 * 32 + bi) * LL + t]);
}

// ---------------------------------------------------------------------------
// K3a: S[bh][l][t] = leaky(ATT_SCALE * dot(q[bh][l], k[bh][t]))
// 128x64 tile, 8l x 4t per thread, packed FMA.
// ---------------------------------------------------------------------------
__global__ __launch_bounds__(256) void qk_gemm(
    const float* __restrict__ q, const float* __restrict__ k,
    float* __restrict__ S)
{
    __shared__ float Qt[32][132];   // [d][l]
    __shared__ float Kt[32][68];    // [d][t]

    int tid = threadIdx.x;
    int bh = blockIdx.z;
    int t0 = blockIdx.x * 64, l0 = blockIdx.y * 128;
    const float* qb = q + (size_t)bh * (LL * DD);
    const float* kb = k + (size_t)bh * (LL * DD);

    {
        int r = tid >> 1, cs = (tid & 1) * 16;
        #pragma unroll
        for (int j = 0; j < 4; j++) {
            float4 v = *(const float4*)(qb + (size_t)(l0 + r) * DD + cs + j * 4);
            Qt[cs + j*4 + 0][r] = v.x; Qt[cs + j*4 + 1][r] = v.y;
            Qt[cs + j*4 + 2][r] = v.z; Qt[cs + j*4 + 3][r] = v.w;
        }
    }
    {
        int r2 = tid & 63, cs2 = (tid >> 6) * 8;
        #pragma unroll
        for (int j = 0; j < 2; j++) {
            float4 v = *(const float4*)(kb + (size_t)(t0 + r2) * DD + cs2 + j * 4);
            Kt[cs2 + j*4 + 0][r2] = v.x; Kt[cs2 + j*4 + 1][r2] = v.y;
            Kt[cs2 + j*4 + 2][r2] = v.z; Kt[cs2 + j*4 + 3][r2] = v.w;
        }
    }
    __syncthreads();

    int lg = (tid >> 4) * 8;
    int tg = (tid & 15) * 4;
    unsigned long long acc2[4][4];
    #pragma unroll
    for (int t = 0; t < 4; t++)
        #pragma unroll
        for (int p = 0; p < 4; p++) acc2[t][p] = 0ULL;

    #pragma unroll
    for (int d = 0; d < 32; d++) {
        ulonglong2 q0 = *(const ulonglong2*)&Qt[d][lg];
        ulonglong2 q1 = *(const ulonglong2*)&Qt[d][lg + 4];
        float4 kv = *(const float4*)&Kt[d][tg];
        const float kl[4] = {kv.x, kv.y, kv.z, kv.w};
        #pragma unroll
        for (int t = 0; t < 4; t++) {
            unsigned long long k2;
            DUP2(k2, kl[t]);
            FMA2(acc2[t][0], q0.x, k2);
            FMA2(acc2[t][1], q0.y, k2);
            FMA2(acc2[t][2], q1.x, k2);
            FMA2(acc2[t][3], q1.y, k2);
        }
    }

    float* Sb = S + (size_t)bh * (LL * LL);
    #pragma unroll
    for (int r = 0; r < 8; r++) {
        float4 o;
        #pragma unroll
        for (int t = 0; t < 4; t++) {
            float lo, hi;
            UNPACK2(lo, hi, acc2[t][r >> 1]);
            float val = ((r & 1) ? hi : lo) * ATT_SCALE;
            ((float*)&o)[t] = (val > 0.f) ? val : 0.01f * val;
        }
        *(float4*)(Sb + (size_t)(l0 + lg + r) * LL + t0 + tg) = o;
    }
}

// ---------------------------------------------------------------------------
// K3b (FUSED softmax, bitmask): A = softmax_t( mask( sum_h R[i,h]*S ) )
// ---------------------------------------------------------------------------
__global__ __launch_bounds__(256) void mix_softmax_kernel(
    const float* __restrict__ S, const unsigned* __restrict__ maskBuf,
    const float* __restrict__ R, float* __restrict__ A_out)
{
    __shared__ float Rs[64];
    __shared__ unsigned Msk[8][32];
    __shared__ float red[8][8];    // [warp][i]
    __shared__ float bc_mx[8];
    __shared__ float bc_ri[8];
    int tid = threadIdx.x, lane = tid & 31, w = tid >> 5;
    int l = blockIdx.x, b = blockIdx.y;
    if (tid < 64) Rs[tid] = R[tid];
    Msk[tid >> 5][tid & 31] =
        maskBuf[((size_t)(b * 8 + (tid >> 5)) * LL + l) * 32 + (tid & 31)];
    __syncthreads();

    int t4 = tid * 4;
    int jbit = (t4 & 127) >> 2;
    int wbase = (t4 >> 7) * 4;
    float4 s[8];
    #pragma unroll
    for (int h = 0; h < 8; h++)
        s[h] = *(const float4*)(S + ((size_t)((b * 8 + h) * LL + l)) * LL + t4);

    float4 o[8];
    float rmax[8];
    #pragma unroll
    for (int i = 0; i < 8; i++) {
        float mx = 0.f, my = 0.f, mz = 0.f, mw = 0.f;
        #pragma unroll
        for (int h = 0; h < 8; h++) {
            float r = Rs[i * 8 + h];
            mx += r * s[h].x; my += r * s[h].y;
            mz += r * s[h].z; mw += r * s[h].w;
        }
        unsigned w0 = Msk[i][wbase + 0], w1 = Msk[i][wbase + 1];
        unsigned w2 = Msk[i][wbase + 2], w3 = Msk[i][wbase + 3];
        o[i].x = ((w0 >> jbit) & 1u) ? mx : -INFINITY;
        o[i].y = ((w1 >> jbit) & 1u) ? my : -INFINITY;
        o[i].z = ((w2 >> jbit) & 1u) ? mz : -INFINITY;
        o[i].w = ((w3 >> jbit) & 1u) ? mw : -INFINITY;
        rmax[i] = fmaxf(fmaxf(o[i].x, o[i].y), fmaxf(o[i].z, o[i].w));
    }

    #pragma unroll
    for (int i = 0; i < 8; i++) {
        float mx = rmax[i];
        #pragma unroll
        for (int off = 16; off; off >>= 1)
            mx = fmaxf(mx, __shfl_down_sync(0xffffffffu, mx, off));
        if (lane == 0) red[w][i] = mx;
    }
    __syncthreads();
    if (tid < 8) {
        float mx = red[0][tid];
        #pragma unroll
        for (int ww = 1; ww < 8; ww++) mx = fmaxf(mx, red[ww][tid]);
        bc_mx[tid] = mx;
    }
    __syncthreads();

    float psum[8];
    #pragma unroll
    for (int i = 0; i < 8; i++) {
        float mx = bc_mx[i];
        o[i].x = __expf(o[i].x - mx);
        o[i].y = __expf(o[i].y - mx);
        o[i].z = __expf(o[i].z - mx);
        o[i].w = __expf(o[i].w - mx);
        psum[i] = (o[i].x + o[i].y) + (o[i].z + o[i].w);
    }
    __syncthreads();
    #pragma unroll
    for (int i = 0; i < 8; i++) {
        float sm = psum[i];
        #pragma unroll
        for (int off = 16; off; off >>= 1)
            sm += __shfl_down_sync(0xffffffffu, sm, off);
        if (lane == 0) red[w][i] = sm;
    }
    __syncthreads();
    if (tid < 8) {
        float sm = 0.f;
        #pragma unroll
        for (int ww = 0; ww < 8; ww++) sm += red[ww][tid];
        bc_ri[tid] = 1.f / sm;
    }
    __syncthreads();

    #pragma unroll
    for (int i = 0; i < 8; i++) {
        float ri = bc_ri[i];
        float4 a;
        a.x = o[i].x * ri; a.y = o[i].y * ri;
        a.z = o[i].z * ri; a.w = o[i].w * ri;
        *(float4*)(A_out + ((size_t)((b * 8 + i) * LL + l)) * LL + t4) = a;
    }
}

// ---------------------------------------------------------------------------
// K5 (FUSED): Ar tile construction + write + GEMM, per (b,h), k-split z.
// ---------------------------------------------------------------------------
__global__ __launch_bounds__(256) void gemm_ar(
    const float* __restrict__ A, const float* __restrict__ rcinv,
    const float* __restrict__ Bm, float* __restrict__ ArOut,
    float* __restrict__ Cp0, float* __restrict__ Cp1)
{
    __shared__ float Ast[32][132];   // [l][t] holding Ar values
    __shared__ float Bs[32][32];     // [l][n]

    int tid = threadIdx.x;
    int bh = blockIdx.y;
    int kz = blockIdx.z;
    int t0 = blockIdx.x * 128;
    const float* Ab  = A + (size_t)bh * (LL * LL);
    const float* Bb  = Bm + (size_t)bh * (LL * DD);
    const float* rcb = rcinv + bh * LL;
    float* Arb = ArOut + (size_t)bh * (LL * LL);
    float* C = (kz ? Cp1 : Cp0) + (size_t)(bh >> 3) * (LL * DIMM);
    int hh = bh & 7;

    int lr = tid >> 3, tseg = (tid & 7) * 16;
    int brow = tid >> 3, bcol = (tid & 7) * 4;
    int rg4 = (tid >> 3) * 4, cg = (tid & 7) * 4;

    unsigned long long acc2[4][2];
    #pragma unroll
    for (int c4 = 0; c4 < 4; c4++) { acc2[c4][0] = 0ULL; acc2[c4][1] = 0ULL; }

    for (int c = 0; c < 16; c++) {
        int l0 = kz * 512 + c * 32;
        #pragma unroll
        for (int j = 0; j < 4; j++) {
            float4 v  = *(const float4*)(Ab + (size_t)(l0 + lr) * LL + t0 + tseg + j * 4);
            float4 rc = *(const float4*)(rcb + t0 + tseg + j * 4);
            float4 ar;
            ar.x = __expf(v.x) * rc.x; ar.y = __expf(v.y) * rc.y;
            ar.z = __expf(v.z) * rc.z; ar.w = __expf(v.w) * rc.w;
            *(float4*)&Ast[lr][tseg + j * 4] = ar;
        }
        *(float4*)&Bs[brow][bcol] =
            *(const float4*)(Bb + (size_t)(l0 + brow) * DD + bcol);
        __syncthreads();

        #pragma unroll
        for (int p = 0; p < 4; p++) {
            int tr = p * 32 + (tid >> 3);
            int lc = (tid & 7) * 4;
            float4 wv;
            wv.x = Ast[lc + 0][tr]; wv.y = Ast[lc + 1][tr];
            wv.z = Ast[lc + 2][tr]; wv.w = Ast[lc + 3][tr];
            *(float4*)(Arb + (size_t)(t0 + tr) * LL + l0 + lc) = wv;
        }

        #pragma unroll
        for (int kk = 0; kk < 32; kk++) {
            ulonglong2 ap = *(const ulonglong2*)&Ast[kk][rg4];
            float4 bv = *(const float4*)&Bs[kk][cg];
            const float bl[4] = {bv.x, bv.y, bv.z, bv.w};
            #pragma unroll
            for (int c4 = 0; c4 < 4; c4++) {
                unsigned long long b2;
                DUP2(b2, bl[c4]);
                FMA2(acc2[c4][0], ap.x, b2);
                FMA2(acc2[c4][1], ap.y, b2);
            }
        }
        __syncthreads();
    }

    #pragma unroll
    for (int r = 0; r < 4; r++) {
        float4 o;
        #pragma unroll
        for (int c4 = 0; c4 < 4; c4++) {
            float lo, hi;
            UNPACK2(lo, hi, acc2[c4][r >> 1]);
            ((float*)&o)[c4] = (r & 1) ? hi : lo;
        }
        *(float4*)(C + (size_t)(t0 + rg4 + r) * DIMM + hh * 32 + cg) = o;
    }
}

// ---------------------------------------------------------------------------
// K6: Out[r,n] = sum_m gelu(Vm[r,m]) * Wp[m,n]. 128x32 tile, 4x4 thread tile.
// ---------------------------------------------------------------------------
__device__ __forceinline__ float gelu_exact(float v)
{
    return 0.5f * v * (1.f + erff(v * 0.70710678118654752f));
}

__global__ __launch_bounds__(256) void out_gemm(
    const float* __restrict__ V0, const float* __restrict__ V1a,
    const float* __restrict__ V1b, const float* __restrict__ Wp,
    float* __restrict__ O0, float* __restrict__ O1)
{
    __shared__ float Gs[32][132];
    __shared__ float Ws[32][32];
    int z = blockIdx.z;
    float* Out = z ? O1 : O0;
    int tid = threadIdx.x;
    int r0 = blockIdx.x * 128, n0 = blockIdx.y * 32;

    int lrow = tid >> 1, cseg = (tid & 1) * 16;
    int brow = tid >> 3, bcol = (tid & 7) * 4;
    int rg4 = (tid >> 3) * 4;
    int cg  = (tid & 7) * 4;

    unsigned long long acc2[4][2];
    #pragma unroll
    for (int c4 = 0; c4 < 4; c4++) { acc2[c4][0] = 0ULL; acc2[c4][1] = 0ULL; }

    for (int k0 = 0; k0 < DIMM; k0 += 32) {
        size_t roff = (size_t)(r0 + lrow) * DIMM + k0 + cseg;
        #pragma unroll
        for (int j = 0; j < 4; j++) {
            float4 a;
            if (z) {
                float4 p0 = *(const float4*)(V1a + roff + j * 4);
                float4 p1 = *(const float4*)(V1b + roff + j * 4);
                a.x = p0.x + p1.x; a.y = p0.y + p1.y;
                a.z = p0.z + p1.z; a.w = p0.w + p1.w;
            } else {
                a = *(const float4*)(V0 + roff + j * 4);
            }
            Gs[cseg + j*4 + 0][lrow] = gelu_exact(a.x);
            Gs[cseg + j*4 + 1][lrow] = gelu_exact(a.y);
            Gs[cseg + j*4 + 2][lrow] = gelu_exact(a.z);
            Gs[cseg + j*4 + 3][lrow] = gelu_exact(a.w);
        }
        *(float4*)&Ws[brow][bcol] =
            *(const float4*)(Wp + (size_t)(k0 + brow) * DIMM + n0 + bcol);
        __syncthreads();

        #pragma unroll
        for (int kk = 0; kk < 32; kk++) {
            ulonglong2 ap = *(const ulonglong2*)&Gs[kk][rg4];
            float4 bv = *(const float4*)&Ws[kk][cg];
            const float bl[4] = {bv.x, bv.y, bv.z, bv.w};
            #pragma unroll
            for (int c4 = 0; c4 < 4; c4++) {
                unsigned long long b2;
                DUP2(b2, bl[c4]);
                FMA2(acc2[c4][0], ap.x, b2);
                FMA2(acc2[c4][1], ap.y, b2);
            }
        }
        __syncthreads();
    }

    #pragma unroll
    for (int r = 0; r < 4; r++) {
        float4 o;
        #pragma unroll
        for (int c4 = 0; c4 < 4; c4++) {
            float lo, hi;
            UNPACK2(lo, hi, acc2[c4][r >> 1]);
            ((float*)&o)[c4] = (r & 1) ? hi : lo;
        }
        *(float4*)(Out + (size_t)(r0 + rg4 + r) * DIMM + n0 + cg) = o;
    }
}

// ---------------------------------------------------------------------------
// Launch. Output layout (float32, reference return order):
//   out [4,1024,256] | out_resize [4,1024,256] | A [4,8,1024,1024] | Ar [...]
// S (QK^T logits) borrows the Ar region until gemm_ar overwrites it.
// ---------------------------------------------------------------------------
extern "C" void kernel_launch(void* const* d_in, const int* in_sizes, int n_in,
                              void* d_out, int out_size)
{
    const float* x    = (const float*)d_in[0];
    const float* rx   = (const float*)d_in[1];
    const float* adj  = (const float*)d_in[2];
    const float* adjr = (const float*)d_in[3];
    const float* Wq   = (const float*)d_in[4];
    const float* Wk   = (const float*)d_in[5];
    const float* Wv   = (const float*)d_in[6];
    const float* R    = (const float*)d_in[7];
    const float* Wp   = (const float*)d_in[8];

    float* out  = (float*)d_out;
    float* outr = out + (size_t)BB * LL * DIMM;
    float* A    = out + (size_t)2 * BB * LL * DIMM;
    float* Ar   = A + (size_t)BB * HH * LL * LL;

    float* s = nullptr;
    cudaGetSymbolAddress((void**)&s, g_scratch);
    unsigned* maskBuf = (unsigned*)(s + OFF_MASK);

    // K1: projections (xq, xk, xv, rv)
    proj_kernel<<<dim3(4096, 4), 256>>>(x, rx, Wq, Wk, Wv, s);

    // K2: q = adj @ xq ; k = adjr @ xk ; emit adjacency bitmask (z=0)
    spmm_binary<<<dim3(128, 32, 2), 256>>>(adj,  s + OFF_XQ, s + OFF_Q,
                                           adjr, s + OFF_XK, s + OFF_K,
                                           maskBuf);

    // K3a: S = leaky(scale * q @ k^T)  -> Ar region (scratch use)
    qk_gemm<<<dim3(16, 8, 32), 256>>>(s + OFF_Q, s + OFF_K, Ar);

    // K3b: R-mix + bitmask + full row softmax -> final A
    mix_softmax_kernel<<<dim3(1024, 4), 256>>>(Ar, maskBuf, R, A);

    // K4: column partials + combine (standalone streaming kernels)
    colsum_kernel<<<dim3(4, 32, 4), 256>>>(A, s + OFF_PCOL);
    rc_combine_kernel<<<128, 256>>>(s + OFF_PCOL, s + OFF_RCINV);

    // v = A @ xv  -- sparse weighted gather (lean)
    spmm_weighted<<<dim3(128, 32), 256>>>(A, s + OFF_XV, s + OFF_VM);

    // K5: fused Ar construction + write + vr GEMM (k-split partials)
    gemm_ar<<<dim3(8, 32, 2), 256>>>(A, s + OFF_RCINV, s + OFF_RV, Ar,
                                     s + OFF_VRA, s + OFF_VRB);

    // K6: out = gelu(v) @ Wp ; out_resize = gelu(vra+vrb) @ Wp
    out_gemm<<<dim3(32, 8, 2), 256>>>(s + OFF_VM, s + OFF_VRA, s + OFF_VRB,
                                      Wp, out, outr);
}